// round 1
// baseline (speedup 1.0000x reference)
#include <cuda_runtime.h>
#include <math.h>

typedef unsigned long long ull;

// Problem constants (fixed shapes per reference)
constexpr int N_PTS   = 65536;
constexpr int N_NEIGH = 32;
constexpr int KP      = 15;
constexpr int IN_F    = 64;
constexpr int OUT_F   = 128;
constexpr int RDIM    = KP * IN_F;          // 960
constexpr float INV_EXT = 1.0f / 0.024f;    // 1 / (1.2*0.1/5)
constexpr float BN_EPS  = 1e-6f;
constexpr float NEG_SLOPE = 0.1f;

// Scratch (device globals: allocation-free per harness rules)
__device__ float g_P[(size_t)N_PTS * RDIM];     // 240 MB weighted features
__device__ float g_psum[256 * OUT_F];
__device__ float g_psq [256 * OUT_F];
__device__ float g_scale[OUT_F];
__device__ float g_bias [OUT_F];

// ---- packed f32x2 helpers (FFMA2: 2 FMAs per issue slot on sm_103a) ----
__device__ __forceinline__ ull pk2(float lo, float hi) {
    ull r; asm("mov.b64 %0, {%1, %2};" : "=l"(r) : "f"(lo), "f"(hi)); return r;
}
__device__ __forceinline__ void up2(ull v, float& lo, float& hi) {
    asm("mov.b64 {%0, %1}, %2;" : "=f"(lo), "=f"(hi) : "l"(v));
}
__device__ __forceinline__ ull fma2(ull a, ull b, ull c) {
    ull d; asm("fma.rn.f32x2 %0, %1, %2, %3;" : "=l"(d) : "l"(a), "l"(b), "l"(c));
    return d;
}

// =====================================================================
// K1: weighted[n, k, i] = sum_m max(0, 1 - |diff(n,m)-kp_k|/ext) * feat[nbr(n,m), i]
// CTA = 16 points x 16 lanes (each lane owns 4 contiguous i), 256 threads.
// =====================================================================
__global__ __launch_bounds__(256) void k1_weighted(
    const float* __restrict__ qp, const float* __restrict__ sp,
    const int*   __restrict__ nbr, const float* __restrict__ feat,
    const float* __restrict__ kpts)
{
    __shared__ float kp_s[16][3];
    __shared__ float qp_s[16][3];
    __shared__ int   nbr_s[16][32];
    __shared__ float w_s[16][32][16];   // K padded to 16 (slot 15 = 0)

    const int t = threadIdx.x;
    const int base = blockIdx.x * 16;

    if (t < 45) kp_s[t / 3][t % 3] = kpts[t];
    if (t >= 64 && t < 112) { int u = t - 64; qp_s[u / 3][u % 3] = qp[base * 3 + u]; }
    ((int*)nbr_s)[t]       = nbr[base * 32 + t];
    ((int*)nbr_s)[t + 256] = nbr[base * 32 + t + 256];
    __syncthreads();

    // Phase B: influence weights for 512 (pt, m) pairs
    #pragma unroll
    for (int pair = t; pair < 512; pair += 256) {
        const int pt = pair >> 5, m = pair & 31;
        const int j = nbr_s[pt][m];
        const float dx = sp[(size_t)j * 3 + 0] - qp_s[pt][0];
        const float dy = sp[(size_t)j * 3 + 1] - qp_s[pt][1];
        const float dz = sp[(size_t)j * 3 + 2] - qp_s[pt][2];
        #pragma unroll
        for (int k = 0; k < KP; k++) {
            const float ax = dx - kp_s[k][0];
            const float ay = dy - kp_s[k][1];
            const float az = dz - kp_s[k][2];
            const float sq = ax * ax + ay * ay + az * az;
            w_s[pt][m][k] = fmaxf(1.0f - sqrtf(sq) * INV_EXT, 0.0f);
        }
        w_s[pt][m][15] = 0.0f;
    }
    __syncthreads();

    // Phase C: accumulate weighted features; lane owns i in [lane*4, lane*4+4)
    const int pt = t >> 4, lane = t & 15;
    const int gpt = base + pt;

    ull acc0[KP], acc1[KP];
    #pragma unroll
    for (int k = 0; k < KP; k++) { acc0[k] = 0ull; acc1[k] = 0ull; }

    int j0 = nbr_s[pt][0];
    float4 f = __ldg(reinterpret_cast<const float4*>(feat + (size_t)j0 * IN_F) + lane);

    #pragma unroll 2
    for (int m = 0; m < 32; m++) {
        float4 fn = f;
        if (m < 31) {
            const int jn = nbr_s[pt][m + 1];
            fn = __ldg(reinterpret_cast<const float4*>(feat + (size_t)jn * IN_F) + lane);
        }
        const ull fxy = pk2(f.x, f.y);
        const ull fzw = pk2(f.z, f.w);
        const float* wrow = w_s[pt][m];
        #pragma unroll
        for (int k = 0; k < KP; k++) {
            const float w = wrow[k];
            const ull wp = pk2(w, w);
            acc0[k] = fma2(wp, fxy, acc0[k]);
            acc1[k] = fma2(wp, fzw, acc1[k]);
        }
        f = fn;
    }

    float* dst = g_P + (size_t)gpt * RDIM + lane * 4;
    #pragma unroll
    for (int k = 0; k < KP; k++) {
        float4 v;
        up2(acc0[k], v.x, v.y);
        up2(acc1[k], v.z, v.w);
        *reinterpret_cast<float4*>(dst + k * IN_F) = v;
    }
}

// =====================================================================
// K2: x[65536,128] = P[65536,960] @ Wf[960,128]  (fp32, FFMA2)
// CTA tile 128x128, K-step 16. 256 threads, each computes 8x8 outputs.
// =====================================================================
__global__ __launch_bounds__(256) void k2_gemm(
    const float* __restrict__ Wf, float* __restrict__ out)
{
    __shared__ float As[16][128];   // As[k][row]
    __shared__ float Bs[16][128];   // Bs[k][col]

    const int t = threadIdx.x;
    const int rowBase = blockIdx.x * 128;
    const int ty = t >> 4, tx = t & 15;

    ull acc[8][4];
    #pragma unroll
    for (int r = 0; r < 8; r++)
        #pragma unroll
        for (int c = 0; c < 4; c++) acc[r][c] = 0ull;

    for (int kk = 0; kk < RDIM; kk += 16) {
        // Load A tile (128 rows x 16 k), store transposed
        #pragma unroll
        for (int q = 0; q < 2; q++) {
            const int idx = t * 2 + q;
            const int row = idx >> 2, c4 = idx & 3;
            float4 v = *reinterpret_cast<const float4*>(
                g_P + (size_t)(rowBase + row) * RDIM + kk + c4 * 4);
            As[c4 * 4 + 0][row] = v.x;
            As[c4 * 4 + 1][row] = v.y;
            As[c4 * 4 + 2][row] = v.z;
            As[c4 * 4 + 3][row] = v.w;
        }
        // Load B tile (16 k x 128 cols), coalesced
        #pragma unroll
        for (int q = 0; q < 2; q++) {
            const int idx = t * 2 + q;
            const int r = idx >> 5, c4 = idx & 31;
            *reinterpret_cast<float4*>(&Bs[r][c4 * 4]) =
                *reinterpret_cast<const float4*>(Wf + (size_t)(kk + r) * OUT_F + c4 * 4);
        }
        __syncthreads();

        #pragma unroll
        for (int k = 0; k < 16; k++) {
            float a[8];
            #pragma unroll
            for (int r = 0; r < 8; r++) a[r] = As[k][ty * 8 + r];
            const float4 b0 = *reinterpret_cast<const float4*>(&Bs[k][tx * 8]);
            const float4 b1 = *reinterpret_cast<const float4*>(&Bs[k][tx * 8 + 4]);
            const ull bp[4] = { pk2(b0.x, b0.y), pk2(b0.z, b0.w),
                                pk2(b1.x, b1.y), pk2(b1.z, b1.w) };
            #pragma unroll
            for (int r = 0; r < 8; r++) {
                const ull ap = pk2(a[r], a[r]);
                #pragma unroll
                for (int c = 0; c < 4; c++) acc[r][c] = fma2(ap, bp[c], acc[r][c]);
            }
        }
        __syncthreads();
    }

    #pragma unroll
    for (int r = 0; r < 8; r++) {
        float4 v0, v1;
        up2(acc[r][0], v0.x, v0.y); up2(acc[r][1], v0.z, v0.w);
        up2(acc[r][2], v1.x, v1.y); up2(acc[r][3], v1.z, v1.w);
        float* o = out + (size_t)(rowBase + ty * 8 + r) * OUT_F + tx * 8;
        *reinterpret_cast<float4*>(o)     = v0;
        *reinterpret_cast<float4*>(o + 4) = v1;
    }
}

// =====================================================================
// K3a: per-block partial column sums / sumsq over 256-row slices
// =====================================================================
__global__ __launch_bounds__(256) void k3a_partial(const float* __restrict__ x)
{
    const int t = threadIdx.x;
    const int c = t & 127, h = t >> 7;
    float s = 0.0f, q = 0.0f;
    const size_t rowBase = (size_t)blockIdx.x * 256;
    for (int r = 0; r < 128; r++) {
        const float v = x[(rowBase + (size_t)r * 2 + h) * OUT_F + c];
        s += v;
        q = fmaf(v, v, q);
    }
    __shared__ float ss[256], sq[256];
    ss[t] = s; sq[t] = q;
    __syncthreads();
    if (t < 128) {
        g_psum[blockIdx.x * OUT_F + t] = ss[t] + ss[t + 128];
        g_psq [blockIdx.x * OUT_F + t] = sq[t] + sq[t + 128];
    }
}

// K3b: finalize mean/var -> scale/bias (1 CTA, 128 threads; deterministic)
__global__ void k3b_finalize(const float* __restrict__ gamma,
                             const float* __restrict__ beta)
{
    const int c = threadIdx.x;
    float s = 0.0f, q = 0.0f;
    for (int b = 0; b < 256; b++) {
        s += g_psum[b * OUT_F + c];
        q += g_psq [b * OUT_F + c];
    }
    const float inv_n = 1.0f / (float)N_PTS;
    const float mean = s * inv_n;
    const float var  = q * inv_n - mean * mean;
    const float sc   = gamma[c] * rsqrtf(var + BN_EPS);
    g_scale[c] = sc;
    g_bias[c]  = beta[c] - mean * sc;
}

// K4: in-place BN affine + LeakyReLU, float4-vectorized
__global__ __launch_bounds__(256) void k4_bnrelu(float* __restrict__ x)
{
    const int i = blockIdx.x * 256 + threadIdx.x;       // one float4 each
    float4 v = reinterpret_cast<float4*>(x)[i];
    const int c0 = (i * 4) & 127;
    const float4 sc = *reinterpret_cast<const float4*>(g_scale + c0);
    const float4 bi = *reinterpret_cast<const float4*>(g_bias + c0);
    v.x = fmaf(v.x, sc.x, bi.x); v.x = (v.x >= 0.0f) ? v.x : NEG_SLOPE * v.x;
    v.y = fmaf(v.y, sc.y, bi.y); v.y = (v.y >= 0.0f) ? v.y : NEG_SLOPE * v.y;
    v.z = fmaf(v.z, sc.z, bi.z); v.z = (v.z >= 0.0f) ? v.z : NEG_SLOPE * v.z;
    v.w = fmaf(v.w, sc.w, bi.w); v.w = (v.w >= 0.0f) ? v.w : NEG_SLOPE * v.w;
    reinterpret_cast<float4*>(x)[i] = v;
}

// =====================================================================
extern "C" void kernel_launch(void* const* d_in, const int* in_sizes, int n_in,
                              void* d_out, int out_size)
{
    const float* qp    = (const float*)d_in[0];   // query_points  [65536,3]
    const float* sp    = (const float*)d_in[1];   // support_points[65536,3]
    const int*   nbr   = (const int*)  d_in[2];   // neighbors     [65536,32]
    const float* feat  = (const float*)d_in[3];   // features      [65536,64]
    const float* kpts  = (const float*)d_in[4];   // kernel_points [15,3]
    const float* Wf    = (const float*)d_in[5];   // W             [15,64,128]
    const float* gamma = (const float*)d_in[6];   // [128]
    const float* beta  = (const float*)d_in[7];   // [128]
    float* out = (float*)d_out;                   // [65536,128]

    k1_weighted<<<N_PTS / 16, 256>>>(qp, sp, nbr, feat, kpts);
    k2_gemm<<<N_PTS / 128, 256>>>(Wf, out);
    k3a_partial<<<256, 256>>>(out);
    k3b_finalize<<<1, 128>>>(gamma, beta);
    k4_bnrelu<<<(N_PTS * OUT_F / 4) / 256, 256>>>(out);
}